// round 13
// baseline (speedup 1.0000x reference)
#include <cuda_runtime.h>
#include <cuda_bf16.h>
#include <cstdint>

// Problem constants
#define Ee 768
#define Ll 768
#define Hh 12
#define HDd 64
#define Bb 8
#define Nn 1024
#define Mm 1024
#define KV 12288           // H*M : K of the dx GEMM
#define KVH 6144           // split-K half
#define KE3 2304           // 3*E augmented K for MLP

// ---------------- scratch (device globals) ----------------
__device__ float g_xn[Bb * Nn * Ee];
__device__ float g_part[Bb * Nn * Ee];                           // dx split-K partial
__device__ __nv_bfloat16 g_sa [(long)Bb * Nn * KV];              // bf16 probs [(b,n)][h*1024+m]
__device__ __nv_bfloat16 g_vtb[(long)Bb * Ee * KV];              // bf16 v [(b,e)][h*1024+m]
__device__ __nv_bfloat16 g_xa [Bb * Nn * Ee];                    // bf16 xn
__device__ __nv_bfloat16 g_ya [Bb * Mm * Ee];                    // bf16 yn
__device__ __nv_bfloat16 g_wvt[(long)(Ee * Hh) * Ee];            // bf16 wv^T [9216][768]
__device__ __nv_bfloat16 g_wqt[Ll * Ee];                         // bf16 wq^T
__device__ __nv_bfloat16 g_wkt[Ll * Ee];                         // bf16 wk^T
__device__ __nv_bfloat16 g_wia[Ll * KE3];                        // aug w_in^T [768][2304]
__device__ __nv_bfloat16 g_woa[Ee * KE3];                        // aug w_out^T [768][2304]
__device__ __nv_bfloat16 g_qbh[(long)Bb * Hh * Nn * HDd];        // q [b][h][n][64]
__device__ __nv_bfloat16 g_kbh[(long)Bb * Hh * Mm * HDd];        // k [b][h][m][64]
__device__ __nv_bfloat16 g_hna[(long)Bb * Nn * KE3];             // aug hn rows [Ah|Ah|Al]
__device__ __nv_bfloat16 g_ta [(long)Bb * Nn * KE3];             // aug relu(t) rows
__device__ float g_h [Bb * Nn * Ee];
__device__ float g_hn[Bb * Nn * Ee];

// ================= helpers =================
__device__ __forceinline__ uint32_t smem_u32(const void* p) {
    uint32_t a;
    asm("{ .reg .u64 t; cvta.to.shared.u64 t, %1; cvt.u32.u64 %0, t; }" : "=r"(a) : "l"(p));
    return a;
}

#define CP_ASYNC16(dst, src) \
    asm volatile("cp.async.cg.shared.global [%0], [%1], 16;" :: "r"(dst), "l"(src))
#define CP_COMMIT() asm volatile("cp.async.commit_group;" ::: "memory")
#define CP_WAIT1()  asm volatile("cp.async.wait_group 1;" ::: "memory")
#define CP_WAIT0()  asm volatile("cp.async.wait_group 0;" ::: "memory")

#define LDSM4(r0, r1, r2, r3, addr) \
    asm volatile("ldmatrix.sync.aligned.m8n8.x4.shared.b16 {%0,%1,%2,%3}, [%4];" \
        : "=r"(r0), "=r"(r1), "=r"(r2), "=r"(r3) : "r"(addr))

#define MMA_BF16(d, a, b) \
    asm volatile("mma.sync.aligned.m16n8k16.row.col.f32.bf16.bf16.f32 " \
        "{%0,%1,%2,%3}, {%4,%5,%6,%7}, {%8,%9}, {%0,%1,%2,%3};" \
        : "+f"((d)[0]), "+f"((d)[1]), "+f"((d)[2]), "+f"((d)[3]) \
        : "r"((a)[0]), "r"((a)[1]), "r"((a)[2]), "r"((a)[3]), "r"((b)[0]), "r"((b)[1]))

// ================= reductions =================
__device__ __forceinline__ float blockReduceSum(float val, float* sbuf) {
    int lane = threadIdx.x & 31, wid = threadIdx.x >> 5;
#pragma unroll
    for (int o = 16; o > 0; o >>= 1) val += __shfl_xor_sync(0xffffffffu, val, o);
    if (lane == 0) sbuf[wid] = val;
    __syncthreads();
    if (wid == 0) {
        float r = (lane < (int)(blockDim.x >> 5)) ? sbuf[lane] : 0.f;
#pragma unroll
        for (int o = 16; o > 0; o >>= 1) r += __shfl_xor_sync(0xffffffffu, r, o);
        if (lane == 0) sbuf[32] = r;
    }
    __syncthreads();
    return sbuf[32];
}

// ================= LayerNorm variants =================
__global__ void ln_bf16_kernel(const float* __restrict__ x, float* __restrict__ o,
                               __nv_bfloat16* __restrict__ ob,
                               const float* __restrict__ g, const float* __restrict__ bt) {
    __shared__ float sbuf[33];
    long row = blockIdx.x;
    const float* p = x + row * Ee;
    int t = threadIdx.x;
    float v0 = p[t], v1 = p[t + 256], v2 = p[t + 512];
    float sum = blockReduceSum(v0 + v1 + v2, sbuf);
    float mean = sum * (1.f / 768.f);
    float d0 = v0 - mean, d1 = v1 - mean, d2 = v2 - mean;
    __syncthreads();
    float sq = blockReduceSum(d0 * d0 + d1 * d1 + d2 * d2, sbuf);
    float rstd = rsqrtf(sq * (1.f / 768.f) + 1e-5f);
    float r0 = d0 * rstd * g[t]       + bt[t];
    float r1 = d1 * rstd * g[t + 256] + bt[t + 256];
    float r2 = d2 * rstd * g[t + 512] + bt[t + 512];
    float* q = o + row * Ee;
    q[t] = r0; q[t + 256] = r1; q[t + 512] = r2;
    __nv_bfloat16* qb2 = ob + row * Ee;
    qb2[t] = __float2bfloat16(r0);
    qb2[t + 256] = __float2bfloat16(r1);
    qb2[t + 512] = __float2bfloat16(r2);
}

// LN3: input = x + x2 (dx split-K partials), outputs fp32 + aug bf16 rows
__global__ void ln_aug_kernel(const float* __restrict__ x, const float* __restrict__ x2,
                              float* __restrict__ o, __nv_bfloat16* __restrict__ oa,
                              const float* __restrict__ g, const float* __restrict__ bt) {
    __shared__ float sbuf[33];
    long row = blockIdx.x;
    const float* p = x + row * Ee;
    const float* p2 = x2 + row * Ee;
    int t = threadIdx.x;
    float v0 = p[t] + p2[t];
    float v1 = p[t + 256] + p2[t + 256];
    float v2 = p[t + 512] + p2[t + 512];
    float sum = blockReduceSum(v0 + v1 + v2, sbuf);
    float mean = sum * (1.f / 768.f);
    float d0 = v0 - mean, d1 = v1 - mean, d2 = v2 - mean;
    __syncthreads();
    float sq = blockReduceSum(d0 * d0 + d1 * d1 + d2 * d2, sbuf);
    float rstd = rsqrtf(sq * (1.f / 768.f) + 1e-5f);
    float r[3];
    r[0] = d0 * rstd * g[t]       + bt[t];
    r[1] = d1 * rstd * g[t + 256] + bt[t + 256];
    r[2] = d2 * rstd * g[t + 512] + bt[t + 512];
    float* q = o + row * Ee;
    q[t] = r[0]; q[t + 256] = r[1]; q[t + 512] = r[2];
    __nv_bfloat16* qa = oa + row * KE3;
#pragma unroll
    for (int i = 0; i < 3; i++) {
        int pos = t + i * 256;
        __nv_bfloat16 hi = __float2bfloat16(r[i]);
        __nv_bfloat16 lo = __float2bfloat16(r[i] - __bfloat162float(hi));
        qa[pos] = hi; qa[768 + pos] = hi; qa[1536 + pos] = lo;
    }
}

// ========== weight transpose convs ==========
__global__ void conv_wt_kernel(const float* __restrict__ w, __nv_bfloat16* __restrict__ wt, int ncols) {
    __shared__ float tile[32][33];
    int k0 = blockIdx.x * 32, n0 = blockIdx.y * 32;
    int tx = threadIdx.x, ty = threadIdx.y;
    tile[ty][tx] = w[(long)(k0 + ty) * ncols + n0 + tx];
    __syncthreads();
    int n = n0 + ty, k = k0 + tx;
    wt[(long)n * Ee + k] = __float2bfloat16(tile[tx][ty]);
}

__global__ void conv_wt_aug_kernel(const float* __restrict__ w, __nv_bfloat16* __restrict__ wt) {
    __shared__ float tile[32][33];
    int k0 = blockIdx.x * 32, n0 = blockIdx.y * 32;
    int tx = threadIdx.x, ty = threadIdx.y;
    tile[ty][tx] = w[(long)(k0 + ty) * Ee + n0 + tx];
    __syncthreads();
    int n = n0 + ty, k = k0 + tx;
    float v = tile[tx][ty];
    __nv_bfloat16 hi = __float2bfloat16(v);
    __nv_bfloat16 lo = __float2bfloat16(v - __bfloat162float(hi));
    __nv_bfloat16* dst = wt + (long)n * KE3;
    dst[k] = hi; dst[768 + k] = lo; dst[1536 + k] = hi;
}

// ================= fused attention probs kernel =================
__global__ void __launch_bounds__(256) attn_probs_kernel(
    const __nv_bfloat16* __restrict__ qbh, const __nv_bfloat16* __restrict__ kbh,
    __nv_bfloat16* __restrict__ sa)
{
    extern __shared__ char dsm[];
    const uint32_t Qs = smem_u32(dsm);
    const uint32_t Ks = Qs + 16384;
    float* mred = (float*)(dsm + 16384 + 131072);
    float* sred = mred + 256;

    const int tid = threadIdx.x, wid = tid >> 5, lane = tid & 31;
    const int n0 = blockIdx.x * 128;
    const int bh = blockIdx.y;
    const int b = bh / Hh, h = bh - b * Hh;

    const __nv_bfloat16* qsrc = qbh + ((long)bh * 1024 + n0) * HDd;
    const __nv_bfloat16* ksrc = kbh + (long)bh * 1024 * HDd;

#pragma unroll
    for (int i = 0; i < 4; i++) {
        int u = tid + 256 * i;
        int row = u >> 3, s = u & 7;
        int ch = s >> 2, sg = s & 3;
        uint32_t dst = Qs + ch * 8192 + row * 64 + (uint32_t)((sg ^ ((row >> 1) & 3)) << 4);
        CP_ASYNC16(dst, qsrc + row * HDd + s * 8);
    }
#pragma unroll
    for (int i = 0; i < 32; i++) {
        int u = tid + 256 * i;
        int row = u >> 3, s = u & 7;
        int mt = row >> 7, rowL = row & 127;
        int ch = s >> 2, sg = s & 3;
        uint32_t dst = Ks + mt * 16384 + ch * 8192 + rowL * 64 + (uint32_t)((sg ^ ((rowL >> 1) & 3)) << 4);
        CP_ASYNC16(dst, ksrc + row * HDd + s * 8);
    }
    CP_COMMIT();
    CP_WAIT0();
    __syncthreads();

    const int wm = wid & 3, wn = wid >> 2;
    const int lrow = lane & 7;
    int rowA[2], rowB[4];
#pragma unroll
    for (int mt = 0; mt < 2; mt++) rowA[mt] = wm * 32 + mt * 16 + ((lane >> 3) & 1) * 8 + lrow;
#pragma unroll
    for (int np = 0; np < 4; np++) rowB[np] = wn * 64 + np * 16 + (lane >> 4) * 8 + lrow;
    const int segAq = (lane >> 4);
    const int segBq = ((lane >> 3) & 1);
    const int r_in = lane >> 2;
    const int c_in = (lane & 3) * 2;

    float rmax[4] = {-1e30f, -1e30f, -1e30f, -1e30f};
    float rsum[4] = {0.f, 0.f, 0.f, 0.f};
    const float sc = 0.125f;

    for (int mt8 = 0; mt8 < 8; mt8++) {
        float acc[2][8][4] = {};
        const uint32_t bTile = Ks + mt8 * 16384;
#pragma unroll
        for (int ch = 0; ch < 2; ch++) {
#pragma unroll
            for (int ks = 0; ks < 2; ks++) {
                uint32_t aF[2][4], bF[8][2];
#pragma unroll
                for (int mt = 0; mt < 2; mt++) {
                    int row = rowA[mt], seg = ks * 2 + segAq;
                    uint32_t ad = Qs + ch * 8192 + row * 64 + (uint32_t)((seg ^ ((row >> 1) & 3)) << 4);
                    LDSM4(aF[mt][0], aF[mt][1], aF[mt][2], aF[mt][3], ad);
                }
#pragma unroll
                for (int np = 0; np < 4; np++) {
                    int row = rowB[np], seg = ks * 2 + segBq;
                    uint32_t bd = bTile + ch * 8192 + row * 64 + (uint32_t)((seg ^ ((row >> 1) & 3)) << 4);
                    LDSM4(bF[2 * np][0], bF[2 * np][1], bF[2 * np + 1][0], bF[2 * np + 1][1], bd);
                }
#pragma unroll
                for (int mt = 0; mt < 2; mt++)
#pragma unroll
                    for (int nt = 0; nt < 8; nt++)
                        MMA_BF16(acc[mt][nt], aF[mt], bF[nt]);
            }
        }
#pragma unroll
        for (int mt = 0; mt < 2; mt++)
#pragma unroll
            for (int half = 0; half < 2; half++) {
                int r = mt * 2 + half;
                float tmax = -1e30f;
#pragma unroll
                for (int nt = 0; nt < 8; nt++)
                    tmax = fmaxf(tmax, fmaxf(acc[mt][nt][half * 2], acc[mt][nt][half * 2 + 1]));
                tmax *= sc;
                tmax = fmaxf(tmax, __shfl_xor_sync(0xffffffffu, tmax, 1));
                tmax = fmaxf(tmax, __shfl_xor_sync(0xffffffffu, tmax, 2));
                float tsum = 0.f;
#pragma unroll
                for (int nt = 0; nt < 8; nt++) {
                    tsum += __expf(acc[mt][nt][half * 2] * sc - tmax);
                    tsum += __expf(acc[mt][nt][half * 2 + 1] * sc - tmax);
                }
                tsum += __shfl_xor_sync(0xffffffffu, tsum, 1);
                tsum += __shfl_xor_sync(0xffffffffu, tsum, 2);
                float nm = fmaxf(rmax[r], tmax);
                rsum[r] = rsum[r] * __expf(rmax[r] - nm) + tsum * __expf(tmax - nm);
                rmax[r] = nm;
            }
    }

    if ((lane & 3) == 0) {
#pragma unroll
        for (int mt = 0; mt < 2; mt++)
#pragma unroll
            for (int half = 0; half < 2; half++) {
                int r = mt * 2 + half;
                int row = wm * 32 + mt * 16 + r_in + half * 8;
                mred[wn * 128 + row] = rmax[r];
                sred[wn * 128 + row] = rsum[r];
            }
    }
    __syncthreads();
    float Mrow[4], Inv[4];
#pragma unroll
    for (int mt = 0; mt < 2; mt++)
#pragma unroll
        for (int half = 0; half < 2; half++) {
            int r = mt * 2 + half;
            int row = wm * 32 + mt * 16 + r_in + half * 8;
            float m0 = mred[row], m1 = mred[128 + row];
            float s0 = sred[row], s1 = sred[128 + row];
            float M = fmaxf(m0, m1);
            float S = s0 * __expf(m0 - M) + s1 * __expf(m1 - M);
            Mrow[r] = M; Inv[r] = 1.f / S;
        }

    __nv_bfloat16* outb = sa + ((long)b * 1024 + n0) * KV + h * 1024;
    for (int mt8 = 0; mt8 < 8; mt8++) {
        float acc[2][8][4] = {};
        const uint32_t bTile = Ks + mt8 * 16384;
#pragma unroll
        for (int ch = 0; ch < 2; ch++) {
#pragma unroll
            for (int ks = 0; ks < 2; ks++) {
                uint32_t aF[2][4], bF[8][2];
#pragma unroll
                for (int mt = 0; mt < 2; mt++) {
                    int row = rowA[mt], seg = ks * 2 + segAq;
                    uint32_t ad = Qs + ch * 8192 + row * 64 + (uint32_t)((seg ^ ((row >> 1) & 3)) << 4);
                    LDSM4(aF[mt][0], aF[mt][1], aF[mt][2], aF[mt][3], ad);
                }
#pragma unroll
                for (int np = 0; np < 4; np++) {
                    int row = rowB[np], seg = ks * 2 + segBq;
                    uint32_t bd = bTile + ch * 8192 + row * 64 + (uint32_t)((seg ^ ((row >> 1) & 3)) << 4);
                    LDSM4(bF[2 * np][0], bF[2 * np][1], bF[2 * np + 1][0], bF[2 * np + 1][1], bd);
                }
#pragma unroll
                for (int mt = 0; mt < 2; mt++)
#pragma unroll
                    for (int nt = 0; nt < 8; nt++)
                        MMA_BF16(acc[mt][nt], aF[mt], bF[nt]);
            }
        }
#pragma unroll
        for (int mt = 0; mt < 2; mt++)
#pragma unroll
            for (int half = 0; half < 2; half++) {
                int r = mt * 2 + half;
                int row = wm * 32 + mt * 16 + r_in + half * 8;
#pragma unroll
                for (int nt = 0; nt < 8; nt++) {
                    int col = mt8 * 128 + wn * 64 + nt * 8 + c_in;
                    float p0 = __expf(acc[mt][nt][half * 2] * sc - Mrow[r]) * Inv[r];
                    float p1 = __expf(acc[mt][nt][half * 2 + 1] * sc - Mrow[r]) * Inv[r];
                    *(__nv_bfloat162*)(outb + (long)row * KV + col) =
                        __nv_bfloat162(__float2bfloat16(p0), __float2bfloat16(p1));
                }
            }
    }
}

// ================= bf16 tensor-core GEMM (R10 config: K-chunk 32, 3-stage static smem) ==
// mode 0: v-proj: smem-transposed coalesced bf16 writes to Cvt[(b*E+e)*KV + h*1024+m]
// mode 1: fp32 out = acc (+bias) + res
// mode 2: q/k dual-source (bz selects {A,Bm,bias,Cvt} vs {A2,B2,bias2,Cvt2}); scatter [b,h,n,64]
// mode 4: relu-aug rows -> Cvt[row*2304 + {col, 768+col}]=hi, [1536+col]=lo
// mode 5: dx split-K: bz=(b<<1)|sp; K offset sp*KVH; sp0: Cf=acc+res; sp1: Cfp=acc
#define TRS 136
__global__ void __launch_bounds__(256) gemm_mma_kernel(
    const __nv_bfloat16* __restrict__ A, const __nv_bfloat16* __restrict__ Bm,
    int Kp, int ldk, long sAb, long sBb,
    const float* __restrict__ bias,
    const float* __restrict__ res, long sRes, float* __restrict__ Cf, long sC, int ldc,
    __nv_bfloat16* __restrict__ Cvt, int mode,
    const __nv_bfloat16* __restrict__ A2, const __nv_bfloat16* __restrict__ B2,
    const float* __restrict__ bias2, __nv_bfloat16* __restrict__ Cvt2,
    float* __restrict__ Cfp)
{
    __shared__ union {
        struct { __nv_bfloat16 A[3][128 * 32]; __nv_bfloat16 B[3][128 * 32]; } p;
        __nv_bfloat16 tr[128 * TRS];
    } sm;
    const int tid = threadIdx.x, wid = tid >> 5, lane = tid & 31;
    const int bz = blockIdx.z;
    const int n0 = blockIdx.x * 128, m0 = blockIdx.y * 128;

    const int b_eff = (mode == 5) ? (bz >> 1) : bz;
    const int sp    = (mode == 5) ? (bz & 1) : 0;
    const float* biasp = bias;
    __nv_bfloat16* CvtP = Cvt;
    const __nv_bfloat16* Asel = A;
    const __nv_bfloat16* Bsel = Bm;
    if (mode == 2 && bz == 1) { Asel = A2; Bsel = B2; biasp = bias2; CvtP = Cvt2; }

    const __nv_bfloat16* Ap = Asel + (long)b_eff * sAb + (long)sp * KVH;
    const __nv_bfloat16* Bp = Bsel + (long)b_eff * sBb + (long)sp * KVH;

    const int isA = (tid < 128);
    const int srow = isA ? tid : tid - 128;
    const __nv_bfloat16* gsrc = isA ? (Ap + (long)(m0 + srow) * ldk)
                                    : (Bp + (long)(n0 + srow) * ldk);
    uint32_t stage0 = smem_u32(isA ? (const void*)&sm.p.A[0][0] : (const void*)&sm.p.B[0][0]) + srow * 64;
    uint32_t dsw[4];
#pragma unroll
    for (int s2 = 0; s2 < 4; s2++) dsw[s2] = (uint32_t)((s2 ^ ((srow >> 1) & 3)) << 4);

    const int nchunks = Kp >> 5;

#pragma unroll
    for (int pc = 0; pc < 2; pc++) {
        if (pc < nchunks) {
            uint32_t d = stage0 + (uint32_t)(pc * 8192);
            const __nv_bfloat16* p = gsrc + (long)pc * 32;
#pragma unroll
            for (int s2 = 0; s2 < 4; s2++) CP_ASYNC16(d + dsw[s2], p + s2 * 8);
            CP_COMMIT();
        }
    }

    const int wm = wid & 3, wn = wid >> 2;
    const int lrow = lane & 7;
    int rowA[2], rowB[4];
#pragma unroll
    for (int mt = 0; mt < 2; mt++) rowA[mt] = wm * 32 + mt * 16 + ((lane >> 3) & 1) * 8 + lrow;
#pragma unroll
    for (int np = 0; np < 4; np++) rowB[np] = wn * 64 + np * 16 + (lane >> 4) * 8 + lrow;
    const int segAq = (lane >> 4);
    const int segBq = ((lane >> 3) & 1);
    const uint32_t smA0 = smem_u32(&sm.p.A[0][0]);
    const uint32_t smB0 = smem_u32(&sm.p.B[0][0]);

    float acc[2][8][4] = {};

    for (int c = 0; c < nchunks; c++) {
        if (c + 1 < nchunks) { CP_WAIT1(); } else { CP_WAIT0(); }
        __syncthreads();
        if (c + 2 < nchunks) {
            const int st = (c + 2) % 3;
            uint32_t d = stage0 + (uint32_t)(st * 8192);
            const __nv_bfloat16* p = gsrc + (long)(c + 2) * 32;
#pragma unroll
            for (int s2 = 0; s2 < 4; s2++) CP_ASYNC16(d + dsw[s2], p + s2 * 8);
            CP_COMMIT();
        }
        const int buf = c % 3;
        const uint32_t aB = smA0 + (uint32_t)(buf * 8192);
        const uint32_t bB = smB0 + (uint32_t)(buf * 8192);
#pragma unroll
        for (int ks = 0; ks < 2; ks++) {
            uint32_t aF[2][4];
            uint32_t bF[8][2];
#pragma unroll
            for (int mt = 0; mt < 2; mt++) {
                int row = rowA[mt], seg = ks * 2 + segAq;
                uint32_t ad = aB + row * 64 + (uint32_t)((seg ^ ((row >> 1) & 3)) << 4);
                LDSM4(aF[mt][0], aF[mt][1], aF[mt][2], aF[mt][3], ad);
            }
#pragma unroll
            for (int np = 0; np < 4; np++) {
                int row = rowB[np], seg = ks * 2 + segBq;
                uint32_t bd = bB + row * 64 + (uint32_t)((seg ^ ((row >> 1) & 3)) << 4);
                LDSM4(bF[2 * np][0], bF[2 * np][1], bF[2 * np + 1][0], bF[2 * np + 1][1], bd);
            }
#pragma unroll
            for (int mt = 0; mt < 2; mt++)
#pragma unroll
                for (int nt = 0; nt < 8; nt++)
                    MMA_BF16(acc[mt][nt], aF[mt], bF[nt]);
        }
        __syncthreads();
    }

    const int r_in = lane >> 2;
    const int c_in = (lane & 3) * 2;

    if (mode == 0) {
#pragma unroll
        for (int mt = 0; mt < 2; mt++)
#pragma unroll
            for (int nt = 0; nt < 8; nt++) {
                int colL = wn * 64 + nt * 8 + c_in;
#pragma unroll
                for (int half = 0; half < 2; half++) {
                    int rowL = wm * 32 + mt * 16 + r_in + half * 8;
                    float v0 = acc[mt][nt][half * 2 + 0] + biasp[n0 + colL];
                    float v1 = acc[mt][nt][half * 2 + 1] + biasp[n0 + colL + 1];
                    sm.tr[colL * TRS + rowL]       = __float2bfloat16(v0);
                    sm.tr[(colL + 1) * TRS + rowL] = __float2bfloat16(v1);
                }
            }
        __syncthreads();
        int col = tid >> 1, seg = tid & 1;
        int cg = n0 + col;
        int h = cg / Ee, e = cg - h * Ee;
        int b = m0 >> 10, mbase = (m0 & 1023) + seg * 64;
        __nv_bfloat16* dst = CvtP + ((long)(b * Ee + e)) * KV + h * 1024 + mbase;
        const __nv_bfloat16* srcp = &sm.tr[col * TRS + seg * 64];
#pragma unroll
        for (int i = 0; i < 8; i++)
            *(float4*)(dst + i * 8) = *(const float4*)(srcp + i * 8);
        return;
    }

#pragma unroll
    for (int mt = 0; mt < 2; mt++) {
#pragma unroll
        for (int nt = 0; nt < 8; nt++) {
            int col0 = n0 + wn * 64 + nt * 8 + c_in;
#pragma unroll
            for (int half = 0; half < 2; half++) {
                int row = m0 + wm * 32 + mt * 16 + r_in + half * 8;
                float v0 = acc[mt][nt][half * 2 + 0];
                float v1 = acc[mt][nt][half * 2 + 1];
                if (mode == 1) {
                    if (biasp) { v0 += biasp[col0]; v1 += biasp[col0 + 1]; }
                    const float* rs = res + (long)b_eff * sRes + (long)row * ldc + col0;
                    float2 rv = *(const float2*)rs;
                    *(float2*)(Cf + (long)b_eff * sC + (long)row * ldc + col0) = make_float2(v0 + rv.x, v1 + rv.y);
                } else if (mode == 5) {
                    long off = (long)b_eff * sC + (long)row * ldc + col0;
                    if (sp == 0) {
                        const float* rs = res + (long)b_eff * sRes + (long)row * ldc + col0;
                        float2 rv = *(const float2*)rs;
                        *(float2*)(Cf + off) = make_float2(v0 + rv.x, v1 + rv.y);
                    } else {
                        *(float2*)(Cfp + off) = make_float2(v0, v1);
                    }
                } else if (mode == 2) {
                    int b = row >> 10, n = row & 1023;
                    v0 += biasp[col0]; v1 += biasp[col0 + 1];
                    int h = col0 >> 6, d = col0 & 63;
                    long addr = (((long)(b * Hh + h) * 1024 + n) << 6) + d;
                    *(__nv_bfloat162*)(CvtP + addr) = __nv_bfloat162(__float2bfloat16(v0), __float2bfloat16(v1));
                } else { // mode 4
                    v0 = fmaxf(v0 + biasp[col0], 0.f);
                    v1 = fmaxf(v1 + biasp[col0 + 1], 0.f);
                    __nv_bfloat16 h0 = __float2bfloat16(v0), h1b = __float2bfloat16(v1);
                    __nv_bfloat16 l0 = __float2bfloat16(v0 - __bfloat162float(h0));
                    __nv_bfloat16 l1 = __float2bfloat16(v1 - __bfloat162float(h1b));
                    __nv_bfloat16* dst = CvtP + (long)row * KE3;
                    __nv_bfloat162 hp = __nv_bfloat162(h0, h1b);
                    *(__nv_bfloat162*)(dst + col0) = hp;
                    *(__nv_bfloat162*)(dst + 768 + col0) = hp;
                    *(__nv_bfloat162*)(dst + 1536 + col0) = __nv_bfloat162(l0, l1);
                }
            }
        }
    }
}

// ================= launch =================
extern "C" void kernel_launch(void* const* d_in, const int* in_sizes, int n_in,
                              void* d_out, int out_size) {
    const float* x     = (const float*)d_in[0];
    const float* y     = (const float*)d_in[1];
    const float* ln1_g = (const float*)d_in[2];
    const float* ln1_b = (const float*)d_in[3];
    const float* ln2_g = (const float*)d_in[4];
    const float* ln2_b = (const float*)d_in[5];
    const float* ln3_g = (const float*)d_in[6];
    const float* ln3_b = (const float*)d_in[7];
    const float* wq    = (const float*)d_in[8];
    const float* bq    = (const float*)d_in[9];
    const float* wk    = (const float*)d_in[10];
    const float* bk    = (const float*)d_in[11];
    const float* wv    = (const float*)d_in[12];
    const float* bv    = (const float*)d_in[13];
    const float* w_in  = (const float*)d_in[14];
    const float* b_in  = (const float*)d_in[15];
    const float* w_out = (const float*)d_in[16];
    const float* b_out = (const float*)d_in[17];

    float* out1 = (float*)d_out;
    float* yn   = out1 + (long)Bb * Nn * Ee;

    float *xn, *hb, *hnb, *part;
    __nv_bfloat16 *sa, *vtb, *xa, *ya, *wvt, *wqt, *wkt, *wia, *woa, *qbh, *kbh, *hna, *ta;
    cudaGetSymbolAddress((void**)&xn,  g_xn);
    cudaGetSymbolAddress((void**)&hb,  g_h);
    cudaGetSymbolAddress((void**)&hnb, g_hn);
    cudaGetSymbolAddress((void**)&part, g_part);
    cudaGetSymbolAddress((void**)&sa,  g_sa);
    cudaGetSymbolAddress((void**)&vtb, g_vtb);
    cudaGetSymbolAddress((void**)&xa,  g_xa);
    cudaGetSymbolAddress((void**)&ya,  g_ya);
    cudaGetSymbolAddress((void**)&wvt, g_wvt);
    cudaGetSymbolAddress((void**)&wqt, g_wqt);
    cudaGetSymbolAddress((void**)&wkt, g_wkt);
    cudaGetSymbolAddress((void**)&wia, g_wia);
    cudaGetSymbolAddress((void**)&woa, g_woa);
    cudaGetSymbolAddress((void**)&qbh, g_qbh);
    cudaGetSymbolAddress((void**)&kbh, g_kbh);
    cudaGetSymbolAddress((void**)&hna, g_hna);
    cudaGetSymbolAddress((void**)&ta,  g_ta);

    static bool attr_done = false;
    if (!attr_done) {
        cudaFuncSetAttribute(attn_probs_kernel, cudaFuncAttributeMaxDynamicSharedMemorySize, 16384 + 131072 + 2048);
        attr_done = true;
    }

    // 1) LayerNorms (fp32 + bf16 copies)
    ln_bf16_kernel<<<Bb * Nn, 256>>>(x, xn, xa, ln1_g, ln1_b);
    ln_bf16_kernel<<<Bb * Mm, 256>>>(y, yn, ya, ln2_g, ln2_b);

    // 2) weight conversions
    {
        dim3 blk(32, 32);
        conv_wt_kernel<<<dim3(24, 288), blk>>>(wv, wvt, Ee * Hh);
        conv_wt_kernel<<<dim3(24, 24), blk>>>(wq, wqt, Ll);
        conv_wt_kernel<<<dim3(24, 24), blk>>>(wk, wkt, Ll);
        conv_wt_aug_kernel<<<dim3(24, 24), blk>>>(w_in, wia);
        conv_wt_aug_kernel<<<dim3(24, 24), blk>>>(w_out, woa);
    }

    // 3) q + k projections merged (z=2 selects source set) -> [b][h][n|m][64]
    {
        dim3 g(Ll / 128, (Bb * Nn) / 128, 2);
        gemm_mma_kernel<<<g, 256>>>(xa, wqt, Ee, Ee, 0, 0, bq,
                                    nullptr, 0, nullptr, 0, 0, qbh, 2,
                                    ya, wkt, bk, kbh, nullptr);
    }

    // 4) v projection -> vtB [(b,e)][h*1024+m]
    {
        dim3 g((Ee * Hh) / 128, (Bb * Mm) / 128);
        gemm_mma_kernel<<<g, 256>>>(ya, wvt, Ee, Ee, 0, 0, bv,
                                    nullptr, 0, nullptr, 0, 0, vtb, 0,
                                    nullptr, nullptr, nullptr, nullptr, nullptr);
    }

    // 5+6) fused scores + softmax -> bf16 probs
    {
        dim3 g(Nn / 128, Bb * Hh);
        attn_probs_kernel<<<g, 256, 16384 + 131072 + 2048>>>(qbh, kbh, sa);
    }

    // 7) dx split-K x2: hb = s@vt[:KVH] + xn ; part = s@vt[KVH:]
    {
        dim3 g(Ee / 128, Nn / 128, Bb * 2);
        gemm_mma_kernel<<<g, 256>>>(sa, vtb, KVH, KV,
                                    (long)Nn * KV, (long)Ee * KV, nullptr,
                                    xn, (long)Nn * Ee, hb, (long)Nn * Ee, Ee,
                                    nullptr, 5,
                                    nullptr, nullptr, nullptr, nullptr, part);
    }

    // 8) LN3 over (hb + part) -> fp32 + aug bf16 rows
    ln_aug_kernel<<<Bb * Nn, 256>>>(hb, part, hnb, hna, ln3_g, ln3_b);

    // 9) MLP (x3-augmented bf16 mma)
    {
        dim3 g(Ll / 128, (Bb * Nn) / 128);
        gemm_mma_kernel<<<g, 256>>>(hna, wia, KE3, KE3, 0, 0, b_in,
                                    nullptr, 0, nullptr, 0, 0, ta, 4,
                                    nullptr, nullptr, nullptr, nullptr, nullptr);
        gemm_mma_kernel<<<g, 256>>>(ta, woa, KE3, KE3, 0, 0, b_out,
                                    hnb, 0, out1, 0, Ee, nullptr, 1,
                                    nullptr, nullptr, nullptr, nullptr, nullptr);
    }
}

// round 15
// speedup vs baseline: 1.7861x; 1.7861x over previous
#include <cuda_runtime.h>
#include <cuda_bf16.h>
#include <cstdint>

// Problem constants
#define Ee 768
#define Ll 768
#define Hh 12
#define HDd 64
#define Bb 8
#define Nn 1024
#define Mm 1024
#define KV 12288           // H*M : K of the dx GEMM
#define KE3 2304           // 3*E augmented K for MLP

// ---------------- scratch (device globals) ----------------
__device__ float g_xn[Bb * Nn * Ee];
__device__ __nv_bfloat16 g_sa [(long)Bb * Nn * KV];              // bf16 probs [(b,n)][h*1024+m]
__device__ __nv_bfloat16 g_vtb[(long)Bb * Ee * KV];              // bf16 v [(b,e)][h*1024+m]
__device__ __nv_bfloat16 g_xa [Bb * Nn * Ee];                    // bf16 xn
__device__ __nv_bfloat16 g_ya [Bb * Mm * Ee];                    // bf16 yn
__device__ __nv_bfloat16 g_wvt[(long)(Ee * Hh) * Ee];            // bf16 wv^T [9216][768]
__device__ __nv_bfloat16 g_wqt[Ll * Ee];                         // bf16 wq^T
__device__ __nv_bfloat16 g_wkt[Ll * Ee];                         // bf16 wk^T
__device__ __nv_bfloat16 g_wia[Ll * KE3];                        // aug w_in^T [768][2304]
__device__ __nv_bfloat16 g_woa[Ee * KE3];                        // aug w_out^T [768][2304]
__device__ __nv_bfloat16 g_qbh[(long)Bb * Hh * Nn * HDd];        // q [b][h][n][64]
__device__ __nv_bfloat16 g_kbh[(long)Bb * Hh * Mm * HDd];        // k [b][h][m][64]
__device__ __nv_bfloat16 g_hna[(long)Bb * Nn * KE3];             // aug hn rows [Ah|Ah|Al]
__device__ __nv_bfloat16 g_ta [(long)Bb * Nn * KE3];             // aug relu(t) rows
__device__ float g_h [Bb * Nn * Ee];
__device__ float g_hn[Bb * Nn * Ee];

// ================= helpers =================
__device__ __forceinline__ uint32_t smem_u32(const void* p) {
    uint32_t a;
    asm("{ .reg .u64 t; cvta.to.shared.u64 t, %1; cvt.u32.u64 %0, t; }" : "=r"(a) : "l"(p));
    return a;
}

#define CP_ASYNC16(dst, src) \
    asm volatile("cp.async.cg.shared.global [%0], [%1], 16;" :: "r"(dst), "l"(src))
#define CP_COMMIT() asm volatile("cp.async.commit_group;" ::: "memory")
#define CP_WAIT1()  asm volatile("cp.async.wait_group 1;" ::: "memory")
#define CP_WAIT0()  asm volatile("cp.async.wait_group 0;" ::: "memory")

#define LDSM4(r0, r1, r2, r3, addr) \
    asm volatile("ldmatrix.sync.aligned.m8n8.x4.shared.b16 {%0,%1,%2,%3}, [%4];" \
        : "=r"(r0), "=r"(r1), "=r"(r2), "=r"(r3) : "r"(addr))

#define MMA_BF16(d, a, b) \
    asm volatile("mma.sync.aligned.m16n8k16.row.col.f32.bf16.bf16.f32 " \
        "{%0,%1,%2,%3}, {%4,%5,%6,%7}, {%8,%9}, {%0,%1,%2,%3};" \
        : "+f"((d)[0]), "+f"((d)[1]), "+f"((d)[2]), "+f"((d)[3]) \
        : "r"((a)[0]), "r"((a)[1]), "r"((a)[2]), "r"((a)[3]), "r"((b)[0]), "r"((b)[1]))

// ================= reductions =================
__device__ __forceinline__ float blockReduceSum(float val, float* sbuf) {
    int lane = threadIdx.x & 31, wid = threadIdx.x >> 5;
#pragma unroll
    for (int o = 16; o > 0; o >>= 1) val += __shfl_xor_sync(0xffffffffu, val, o);
    if (lane == 0) sbuf[wid] = val;
    __syncthreads();
    if (wid == 0) {
        float r = (lane < (int)(blockDim.x >> 5)) ? sbuf[lane] : 0.f;
#pragma unroll
        for (int o = 16; o > 0; o >>= 1) r += __shfl_xor_sync(0xffffffffu, r, o);
        if (lane == 0) sbuf[32] = r;
    }
    __syncthreads();
    return sbuf[32];
}

// ================= LayerNorm variants =================
__global__ void ln_bf16_kernel(const float* __restrict__ x, float* __restrict__ o,
                               __nv_bfloat16* __restrict__ ob,
                               const float* __restrict__ g, const float* __restrict__ bt) {
    __shared__ float sbuf[33];
    long row = blockIdx.x;
    const float* p = x + row * Ee;
    int t = threadIdx.x;
    float v0 = p[t], v1 = p[t + 256], v2 = p[t + 512];
    float sum = blockReduceSum(v0 + v1 + v2, sbuf);
    float mean = sum * (1.f / 768.f);
    float d0 = v0 - mean, d1 = v1 - mean, d2 = v2 - mean;
    __syncthreads();
    float sq = blockReduceSum(d0 * d0 + d1 * d1 + d2 * d2, sbuf);
    float rstd = rsqrtf(sq * (1.f / 768.f) + 1e-5f);
    float r0 = d0 * rstd * g[t]       + bt[t];
    float r1 = d1 * rstd * g[t + 256] + bt[t + 256];
    float r2 = d2 * rstd * g[t + 512] + bt[t + 512];
    float* q = o + row * Ee;
    q[t] = r0; q[t + 256] = r1; q[t + 512] = r2;
    __nv_bfloat16* qb2 = ob + row * Ee;
    qb2[t] = __float2bfloat16(r0);
    qb2[t + 256] = __float2bfloat16(r1);
    qb2[t + 512] = __float2bfloat16(r2);
}

__global__ void ln_aug_kernel(const float* __restrict__ x, float* __restrict__ o,
                              __nv_bfloat16* __restrict__ oa,
                              const float* __restrict__ g, const float* __restrict__ bt) {
    __shared__ float sbuf[33];
    long row = blockIdx.x;
    const float* p = x + row * Ee;
    int t = threadIdx.x;
    float v0 = p[t], v1 = p[t + 256], v2 = p[t + 512];
    float sum = blockReduceSum(v0 + v1 + v2, sbuf);
    float mean = sum * (1.f / 768.f);
    float d0 = v0 - mean, d1 = v1 - mean, d2 = v2 - mean;
    __syncthreads();
    float sq = blockReduceSum(d0 * d0 + d1 * d1 + d2 * d2, sbuf);
    float rstd = rsqrtf(sq * (1.f / 768.f) + 1e-5f);
    float r[3];
    r[0] = d0 * rstd * g[t]       + bt[t];
    r[1] = d1 * rstd * g[t + 256] + bt[t + 256];
    r[2] = d2 * rstd * g[t + 512] + bt[t + 512];
    float* q = o + row * Ee;
    q[t] = r[0]; q[t + 256] = r[1]; q[t + 512] = r[2];
    __nv_bfloat16* qa = oa + row * KE3;
#pragma unroll
    for (int i = 0; i < 3; i++) {
        int pos = t + i * 256;
        __nv_bfloat16 hi = __float2bfloat16(r[i]);
        __nv_bfloat16 lo = __float2bfloat16(r[i] - __bfloat162float(hi));
        qa[pos] = hi; qa[768 + pos] = hi; qa[1536 + pos] = lo;
    }
}

// ========== weight transpose convs ==========
__global__ void conv_wt_kernel(const float* __restrict__ w, __nv_bfloat16* __restrict__ wt, int ncols) {
    __shared__ float tile[32][33];
    int k0 = blockIdx.x * 32, n0 = blockIdx.y * 32;
    int tx = threadIdx.x, ty = threadIdx.y;
    tile[ty][tx] = w[(long)(k0 + ty) * ncols + n0 + tx];
    __syncthreads();
    int n = n0 + ty, k = k0 + tx;
    wt[(long)n * Ee + k] = __float2bfloat16(tile[tx][ty]);
}

__global__ void conv_wt_aug_kernel(const float* __restrict__ w, __nv_bfloat16* __restrict__ wt) {
    __shared__ float tile[32][33];
    int k0 = blockIdx.x * 32, n0 = blockIdx.y * 32;
    int tx = threadIdx.x, ty = threadIdx.y;
    tile[ty][tx] = w[(long)(k0 + ty) * Ee + n0 + tx];
    __syncthreads();
    int n = n0 + ty, k = k0 + tx;
    float v = tile[tx][ty];
    __nv_bfloat16 hi = __float2bfloat16(v);
    __nv_bfloat16 lo = __float2bfloat16(v - __bfloat162float(hi));
    __nv_bfloat16* dst = wt + (long)n * KE3;
    dst[k] = hi; dst[768 + k] = lo; dst[1536 + k] = hi;
}

// ================= fused attention probs kernel =================
__global__ void __launch_bounds__(256) attn_probs_kernel(
    const __nv_bfloat16* __restrict__ qbh, const __nv_bfloat16* __restrict__ kbh,
    __nv_bfloat16* __restrict__ sa)
{
    extern __shared__ char dsm[];
    const uint32_t Qs = smem_u32(dsm);
    const uint32_t Ks = Qs + 16384;
    float* mred = (float*)(dsm + 16384 + 131072);   // [2][128]
    float* sred = mred + 256;

    const int tid = threadIdx.x, wid = tid >> 5, lane = tid & 31;
    const int n0 = blockIdx.x * 128;
    const int bh = blockIdx.y;
    const int b = bh / Hh, h = bh - b * Hh;

    const __nv_bfloat16* qsrc = qbh + ((long)bh * 1024 + n0) * HDd;
    const __nv_bfloat16* ksrc = kbh + (long)bh * 1024 * HDd;

#pragma unroll
    for (int i = 0; i < 4; i++) {
        int u = tid + 256 * i;
        int row = u >> 3, s = u & 7;
        int ch = s >> 2, sg = s & 3;
        uint32_t dst = Qs + ch * 8192 + row * 64 + (uint32_t)((sg ^ ((row >> 1) & 3)) << 4);
        CP_ASYNC16(dst, qsrc + row * HDd + s * 8);
    }
#pragma unroll
    for (int i = 0; i < 32; i++) {
        int u = tid + 256 * i;
        int row = u >> 3, s = u & 7;
        int mt = row >> 7, rowL = row & 127;
        int ch = s >> 2, sg = s & 3;
        uint32_t dst = Ks + mt * 16384 + ch * 8192 + rowL * 64 + (uint32_t)((sg ^ ((rowL >> 1) & 3)) << 4);
        CP_ASYNC16(dst, ksrc + row * HDd + s * 8);
    }
    CP_COMMIT();
    CP_WAIT0();
    __syncthreads();

    const int wm = wid & 3, wn = wid >> 2;
    const int lrow = lane & 7;
    int rowA[2], rowB[4];
#pragma unroll
    for (int mt = 0; mt < 2; mt++) rowA[mt] = wm * 32 + mt * 16 + ((lane >> 3) & 1) * 8 + lrow;
#pragma unroll
    for (int np = 0; np < 4; np++) rowB[np] = wn * 64 + np * 16 + (lane >> 4) * 8 + lrow;
    const int segAq = (lane >> 4);
    const int segBq = ((lane >> 3) & 1);
    const int r_in = lane >> 2;
    const int c_in = (lane & 3) * 2;

    float rmax[4] = {-1e30f, -1e30f, -1e30f, -1e30f};
    float rsum[4] = {0.f, 0.f, 0.f, 0.f};
    const float sc = 0.125f;

    for (int mt8 = 0; mt8 < 8; mt8++) {
        float acc[2][8][4] = {};
        const uint32_t bTile = Ks + mt8 * 16384;
#pragma unroll
        for (int ch = 0; ch < 2; ch++) {
#pragma unroll
            for (int ks = 0; ks < 2; ks++) {
                uint32_t aF[2][4], bF[8][2];
#pragma unroll
                for (int mt = 0; mt < 2; mt++) {
                    int row = rowA[mt], seg = ks * 2 + segAq;
                    uint32_t ad = Qs + ch * 8192 + row * 64 + (uint32_t)((seg ^ ((row >> 1) & 3)) << 4);
                    LDSM4(aF[mt][0], aF[mt][1], aF[mt][2], aF[mt][3], ad);
                }
#pragma unroll
                for (int np = 0; np < 4; np++) {
                    int row = rowB[np], seg = ks * 2 + segBq;
                    uint32_t bd = bTile + ch * 8192 + row * 64 + (uint32_t)((seg ^ ((row >> 1) & 3)) << 4);
                    LDSM4(bF[2 * np][0], bF[2 * np][1], bF[2 * np + 1][0], bF[2 * np + 1][1], bd);
                }
#pragma unroll
                for (int mt = 0; mt < 2; mt++)
#pragma unroll
                    for (int nt = 0; nt < 8; nt++)
                        MMA_BF16(acc[mt][nt], aF[mt], bF[nt]);
            }
        }
#pragma unroll
        for (int mt = 0; mt < 2; mt++)
#pragma unroll
            for (int half = 0; half < 2; half++) {
                int r = mt * 2 + half;
                float tmax = -1e30f;
#pragma unroll
                for (int nt = 0; nt < 8; nt++)
                    tmax = fmaxf(tmax, fmaxf(acc[mt][nt][half * 2], acc[mt][nt][half * 2 + 1]));
                tmax *= sc;
                tmax = fmaxf(tmax, __shfl_xor_sync(0xffffffffu, tmax, 1));
                tmax = fmaxf(tmax, __shfl_xor_sync(0xffffffffu, tmax, 2));
                float tsum = 0.f;
#pragma unroll
                for (int nt = 0; nt < 8; nt++) {
                    tsum += __expf(acc[mt][nt][half * 2] * sc - tmax);
                    tsum += __expf(acc[mt][nt][half * 2 + 1] * sc - tmax);
                }
                tsum += __shfl_xor_sync(0xffffffffu, tsum, 1);
                tsum += __shfl_xor_sync(0xffffffffu, tsum, 2);
                float nm = fmaxf(rmax[r], tmax);
                rsum[r] = rsum[r] * __expf(rmax[r] - nm) + tsum * __expf(tmax - nm);
                rmax[r] = nm;
            }
    }

    if ((lane & 3) == 0) {
#pragma unroll
        for (int mt = 0; mt < 2; mt++)
#pragma unroll
            for (int half = 0; half < 2; half++) {
                int r = mt * 2 + half;
                int row = wm * 32 + mt * 16 + r_in + half * 8;
                mred[wn * 128 + row] = rmax[r];
                sred[wn * 128 + row] = rsum[r];
            }
    }
    __syncthreads();
    float Mrow[4], Inv[4];
#pragma unroll
    for (int mt = 0; mt < 2; mt++)
#pragma unroll
        for (int half = 0; half < 2; half++) {
            int r = mt * 2 + half;
            int row = wm * 32 + mt * 16 + r_in + half * 8;
            float m0 = mred[row], m1 = mred[128 + row];
            float s0 = sred[row], s1 = sred[128 + row];
            float M = fmaxf(m0, m1);
            float S = s0 * __expf(m0 - M) + s1 * __expf(m1 - M);
            Mrow[r] = M; Inv[r] = 1.f / S;
        }

    __nv_bfloat16* outb = sa + ((long)b * 1024 + n0) * KV + h * 1024;
    for (int mt8 = 0; mt8 < 8; mt8++) {
        float acc[2][8][4] = {};
        const uint32_t bTile = Ks + mt8 * 16384;
#pragma unroll
        for (int ch = 0; ch < 2; ch++) {
#pragma unroll
            for (int ks = 0; ks < 2; ks++) {
                uint32_t aF[2][4], bF[8][2];
#pragma unroll
                for (int mt = 0; mt < 2; mt++) {
                    int row = rowA[mt], seg = ks * 2 + segAq;
                    uint32_t ad = Qs + ch * 8192 + row * 64 + (uint32_t)((seg ^ ((row >> 1) & 3)) << 4);
                    LDSM4(aF[mt][0], aF[mt][1], aF[mt][2], aF[mt][3], ad);
                }
#pragma unroll
                for (int np = 0; np < 4; np++) {
                    int row = rowB[np], seg = ks * 2 + segBq;
                    uint32_t bd = bTile + ch * 8192 + row * 64 + (uint32_t)((seg ^ ((row >> 1) & 3)) << 4);
                    LDSM4(bF[2 * np][0], bF[2 * np][1], bF[2 * np + 1][0], bF[2 * np + 1][1], bd);
                }
#pragma unroll
                for (int mt = 0; mt < 2; mt++)
#pragma unroll
                    for (int nt = 0; nt < 8; nt++)
                        MMA_BF16(acc[mt][nt], aF[mt], bF[nt]);
            }
        }
#pragma unroll
        for (int mt = 0; mt < 2; mt++)
#pragma unroll
            for (int half = 0; half < 2; half++) {
                int r = mt * 2 + half;
                int row = wm * 32 + mt * 16 + r_in + half * 8;
#pragma unroll
                for (int nt = 0; nt < 8; nt++) {
                    int col = mt8 * 128 + wn * 64 + nt * 8 + c_in;
                    float p0 = __expf(acc[mt][nt][half * 2] * sc - Mrow[r]) * Inv[r];
                    float p1 = __expf(acc[mt][nt][half * 2 + 1] * sc - Mrow[r]) * Inv[r];
                    *(__nv_bfloat162*)(outb + (long)row * KV + col) =
                        __nv_bfloat162(__float2bfloat16(p0), __float2bfloat16(p1));
                }
            }
    }
}

// ================= bf16 tensor-core GEMM via mma.sync =================
// 3-stage cp.async pipeline, one __syncthreads per 32-K chunk.  (R10 config, occupancy pinned)
// mode 0: v-proj: smem-transposed coalesced bf16 writes to Cvt[(b*E+e)*KV + h*1024+m]
// mode 1: fp32 out = acc (+bias) + res
// mode 2: q/k scatter: bf16(acc+bias) -> Cvt[((b*H+h)*1024+n)*64+d]
// mode 4: relu-aug rows -> Cvt[row*2304 + {col, 768+col}]=hi, [1536+col]=lo
#define TRS 136
__global__ void __launch_bounds__(256, 2) gemm_mma_kernel(
    const __nv_bfloat16* __restrict__ A, const __nv_bfloat16* __restrict__ Bm,
    int Kp, long sAb, long sBb,
    const float* __restrict__ bias,
    const float* __restrict__ res, long sRes, float* __restrict__ Cf, long sC, int ldc,
    __nv_bfloat16* __restrict__ Cvt, int mode)
{
    __shared__ union {
        struct { __nv_bfloat16 A[3][128 * 32]; __nv_bfloat16 B[3][128 * 32]; } p;
        __nv_bfloat16 tr[128 * TRS];
    } sm;
    const int tid = threadIdx.x, wid = tid >> 5, lane = tid & 31;
    const int bz = blockIdx.z;
    const int n0 = blockIdx.x * 128, m0 = blockIdx.y * 128;
    const __nv_bfloat16* Ap = A + (long)bz * sAb;
    const __nv_bfloat16* Bp = Bm + (long)bz * sBb;

    const int isA = (tid < 128);
    const int srow = isA ? tid : tid - 128;
    const __nv_bfloat16* gsrc = isA ? (Ap + (long)(m0 + srow) * Kp)
                                    : (Bp + (long)(n0 + srow) * Kp);
    uint32_t stage0 = smem_u32(isA ? (const void*)&sm.p.A[0][0] : (const void*)&sm.p.B[0][0]) + srow * 64;
    uint32_t dsw[4];
#pragma unroll
    for (int s2 = 0; s2 < 4; s2++) dsw[s2] = (uint32_t)((s2 ^ ((srow >> 1) & 3)) << 4);

    const int nchunks = Kp >> 5;

#pragma unroll
    for (int pc = 0; pc < 2; pc++) {
        if (pc < nchunks) {
            uint32_t d = stage0 + (uint32_t)(pc * 8192);
            const __nv_bfloat16* p = gsrc + (long)pc * 32;
#pragma unroll
            for (int s2 = 0; s2 < 4; s2++) CP_ASYNC16(d + dsw[s2], p + s2 * 8);
            CP_COMMIT();
        }
    }

    const int wm = wid & 3, wn = wid >> 2;
    const int lrow = lane & 7;
    int rowA[2], rowB[4];
#pragma unroll
    for (int mt = 0; mt < 2; mt++) rowA[mt] = wm * 32 + mt * 16 + ((lane >> 3) & 1) * 8 + lrow;
#pragma unroll
    for (int np = 0; np < 4; np++) rowB[np] = wn * 64 + np * 16 + (lane >> 4) * 8 + lrow;
    const int segAq = (lane >> 4);
    const int segBq = ((lane >> 3) & 1);
    const uint32_t smA0 = smem_u32(&sm.p.A[0][0]);
    const uint32_t smB0 = smem_u32(&sm.p.B[0][0]);

    float acc[2][8][4] = {};

    for (int c = 0; c < nchunks; c++) {
        if (c + 1 < nchunks) { CP_WAIT1(); } else { CP_WAIT0(); }
        __syncthreads();
        if (c + 2 < nchunks) {
            const int st = (c + 2) % 3;
            uint32_t d = stage0 + (uint32_t)(st * 8192);
            const __nv_bfloat16* p = gsrc + (long)(c + 2) * 32;
#pragma unroll
            for (int s2 = 0; s2 < 4; s2++) CP_ASYNC16(d + dsw[s2], p + s2 * 8);
            CP_COMMIT();
        }
        const int buf = c % 3;
        const uint32_t aB = smA0 + (uint32_t)(buf * 8192);
        const uint32_t bB = smB0 + (uint32_t)(buf * 8192);
#pragma unroll
        for (int ks = 0; ks < 2; ks++) {
            uint32_t aF[2][4];
            uint32_t bF[8][2];
#pragma unroll
            for (int mt = 0; mt < 2; mt++) {
                int row = rowA[mt], seg = ks * 2 + segAq;
                uint32_t ad = aB + row * 64 + (uint32_t)((seg ^ ((row >> 1) & 3)) << 4);
                LDSM4(aF[mt][0], aF[mt][1], aF[mt][2], aF[mt][3], ad);
            }
#pragma unroll
            for (int np = 0; np < 4; np++) {
                int row = rowB[np], seg = ks * 2 + segBq;
                uint32_t bd = bB + row * 64 + (uint32_t)((seg ^ ((row >> 1) & 3)) << 4);
                LDSM4(bF[2 * np][0], bF[2 * np][1], bF[2 * np + 1][0], bF[2 * np + 1][1], bd);
            }
#pragma unroll
            for (int mt = 0; mt < 2; mt++)
#pragma unroll
                for (int nt = 0; nt < 8; nt++)
                    MMA_BF16(acc[mt][nt], aF[mt], bF[nt]);
        }
        __syncthreads();
    }

    const int r_in = lane >> 2;
    const int c_in = (lane & 3) * 2;

    if (mode == 0) {
#pragma unroll
        for (int mt = 0; mt < 2; mt++)
#pragma unroll
            for (int nt = 0; nt < 8; nt++) {
                int colL = wn * 64 + nt * 8 + c_in;
#pragma unroll
                for (int half = 0; half < 2; half++) {
                    int rowL = wm * 32 + mt * 16 + r_in + half * 8;
                    float v0 = acc[mt][nt][half * 2 + 0] + bias[n0 + colL];
                    float v1 = acc[mt][nt][half * 2 + 1] + bias[n0 + colL + 1];
                    sm.tr[colL * TRS + rowL]       = __float2bfloat16(v0);
                    sm.tr[(colL + 1) * TRS + rowL] = __float2bfloat16(v1);
                }
            }
        __syncthreads();
        int col = tid >> 1, seg = tid & 1;
        int cg = n0 + col;
        int h = cg / Ee, e = cg - h * Ee;
        int b = m0 >> 10, mbase = (m0 & 1023) + seg * 64;
        __nv_bfloat16* dst = Cvt + ((long)(b * Ee + e)) * KV + h * 1024 + mbase;
        const __nv_bfloat16* srcp = &sm.tr[col * TRS + seg * 64];
#pragma unroll
        for (int i = 0; i < 8; i++)
            *(float4*)(dst + i * 8) = *(const float4*)(srcp + i * 8);
        return;
    }

#pragma unroll
    for (int mt = 0; mt < 2; mt++) {
#pragma unroll
        for (int nt = 0; nt < 8; nt++) {
            int col0 = n0 + wn * 64 + nt * 8 + c_in;
#pragma unroll
            for (int half = 0; half < 2; half++) {
                int row = m0 + wm * 32 + mt * 16 + r_in + half * 8;
                float v0 = acc[mt][nt][half * 2 + 0];
                float v1 = acc[mt][nt][half * 2 + 1];
                if (mode == 1) {
                    if (bias) { v0 += bias[col0]; v1 += bias[col0 + 1]; }
                    const float* rs = res + (long)bz * sRes + (long)row * ldc + col0;
                    float2 rv = *(const float2*)rs;
                    *(float2*)(Cf + (long)bz * sC + (long)row * ldc + col0) = make_float2(v0 + rv.x, v1 + rv.y);
                } else if (mode == 2) {
                    int b = row >> 10, n = row & 1023;
                    v0 += bias[col0]; v1 += bias[col0 + 1];
                    int h = col0 >> 6, d = col0 & 63;
                    long addr = (((long)(b * Hh + h) * 1024 + n) << 6) + d;
                    *(__nv_bfloat162*)(Cvt + addr) = __nv_bfloat162(__float2bfloat16(v0), __float2bfloat16(v1));
                } else { // mode 4
                    v0 = fmaxf(v0 + bias[col0], 0.f);
                    v1 = fmaxf(v1 + bias[col0 + 1], 0.f);
                    __nv_bfloat16 h0 = __float2bfloat16(v0), h1b = __float2bfloat16(v1);
                    __nv_bfloat16 l0 = __float2bfloat16(v0 - __bfloat162float(h0));
                    __nv_bfloat16 l1 = __float2bfloat16(v1 - __bfloat162float(h1b));
                    __nv_bfloat16* dst = Cvt + (long)row * KE3;
                    __nv_bfloat162 hp = __nv_bfloat162(h0, h1b);
                    *(__nv_bfloat162*)(dst + col0) = hp;
                    *(__nv_bfloat162*)(dst + 768 + col0) = hp;
                    *(__nv_bfloat162*)(dst + 1536 + col0) = __nv_bfloat162(l0, l1);
                }
            }
        }
    }
}

// ================= launch =================
extern "C" void kernel_launch(void* const* d_in, const int* in_sizes, int n_in,
                              void* d_out, int out_size) {
    const float* x     = (const float*)d_in[0];
    const float* y     = (const float*)d_in[1];
    const float* ln1_g = (const float*)d_in[2];
    const float* ln1_b = (const float*)d_in[3];
    const float* ln2_g = (const float*)d_in[4];
    const float* ln2_b = (const float*)d_in[5];
    const float* ln3_g = (const float*)d_in[6];
    const float* ln3_b = (const float*)d_in[7];
    const float* wq    = (const float*)d_in[8];
    const float* bq    = (const float*)d_in[9];
    const float* wk    = (const float*)d_in[10];
    const float* bk    = (const float*)d_in[11];
    const float* wv    = (const float*)d_in[12];
    const float* bv    = (const float*)d_in[13];
    const float* w_in  = (const float*)d_in[14];
    const float* b_in  = (const float*)d_in[15];
    const float* w_out = (const float*)d_in[16];
    const float* b_out = (const float*)d_in[17];

    float* out1 = (float*)d_out;
    float* yn   = out1 + (long)Bb * Nn * Ee;

    float *xn, *hb, *hnb;
    __nv_bfloat16 *sa, *vtb, *xa, *ya, *wvt, *wqt, *wkt, *wia, *woa, *qbh, *kbh, *hna, *ta;
    cudaGetSymbolAddress((void**)&xn,  g_xn);
    cudaGetSymbolAddress((void**)&hb,  g_h);
    cudaGetSymbolAddress((void**)&hnb, g_hn);
    cudaGetSymbolAddress((void**)&sa,  g_sa);
    cudaGetSymbolAddress((void**)&vtb, g_vtb);
    cudaGetSymbolAddress((void**)&xa,  g_xa);
    cudaGetSymbolAddress((void**)&ya,  g_ya);
    cudaGetSymbolAddress((void**)&wvt, g_wvt);
    cudaGetSymbolAddress((void**)&wqt, g_wqt);
    cudaGetSymbolAddress((void**)&wkt, g_wkt);
    cudaGetSymbolAddress((void**)&wia, g_wia);
    cudaGetSymbolAddress((void**)&woa, g_woa);
    cudaGetSymbolAddress((void**)&qbh, g_qbh);
    cudaGetSymbolAddress((void**)&kbh, g_kbh);
    cudaGetSymbolAddress((void**)&hna, g_hna);
    cudaGetSymbolAddress((void**)&ta,  g_ta);

    static bool attr_done = false;
    if (!attr_done) {
        cudaFuncSetAttribute(attn_probs_kernel, cudaFuncAttributeMaxDynamicSharedMemorySize, 16384 + 131072 + 2048);
        attr_done = true;
    }

    // 1) LayerNorms (fp32 + bf16 copies)
    ln_bf16_kernel<<<Bb * Nn, 256>>>(x, xn, xa, ln1_g, ln1_b);
    ln_bf16_kernel<<<Bb * Mm, 256>>>(y, yn, ya, ln2_g, ln2_b);

    // 2) weight conversions
    {
        dim3 blk(32, 32);
        conv_wt_kernel<<<dim3(24, 288), blk>>>(wv, wvt, Ee * Hh);
        conv_wt_kernel<<<dim3(24, 24), blk>>>(wq, wqt, Ll);
        conv_wt_kernel<<<dim3(24, 24), blk>>>(wk, wkt, Ll);
        conv_wt_aug_kernel<<<dim3(24, 24), blk>>>(w_in, wia);
        conv_wt_aug_kernel<<<dim3(24, 24), blk>>>(w_out, woa);
    }

    // 3) q, k projections (bf16 mma) -> [b][h][n][64]
    {
        dim3 g(Ll / 128, (Bb * Nn) / 128);
        gemm_mma_kernel<<<g, 256>>>(xa, wqt, Ee, 0, 0, bq, nullptr, 0, nullptr, 0, 0, qbh, 2);
        gemm_mma_kernel<<<g, 256>>>(ya, wkt, Ee, 0, 0, bk, nullptr, 0, nullptr, 0, 0, kbh, 2);
    }

    // 4) v projection (bf16 mma) -> vtB [(b,e)][h*1024+m]
    {
        dim3 g((Ee * Hh) / 128, (Bb * Mm) / 128);
        gemm_mma_kernel<<<g, 256>>>(ya, wvt, Ee, 0, 0, bv, nullptr, 0, nullptr, 0, 0, vtb, 0);
    }

    // 5+6) fused scores + softmax -> bf16 probs
    {
        dim3 g(Nn / 128, Bb * Hh);
        attn_probs_kernel<<<g, 256, 16384 + 131072 + 2048>>>(qbh, kbh, sa);
    }

    // 7) dx (bf16 mma): h = s @ vt + xn
    {
        dim3 g(Ee / 128, Nn / 128, Bb);
        gemm_mma_kernel<<<g, 256>>>(sa, vtb, KV,
                                    (long)Nn * KV, (long)Ee * KV, nullptr,
                                    xn, (long)Nn * Ee, hb, (long)Nn * Ee, Ee,
                                    nullptr, 1);
    }

    // 8) LN3 (fp32 + aug bf16 rows)
    ln_aug_kernel<<<Bb * Nn, 256>>>(hb, hnb, hna, ln3_g, ln3_b);

    // 9) MLP (x3-augmented bf16 mma)
    {
        dim3 g(Ll / 128, (Bb * Nn) / 128);
        gemm_mma_kernel<<<g, 256>>>(hna, wia, KE3, 0, 0, b_in, nullptr, 0, nullptr, 0, 0, ta, 4);
        gemm_mma_kernel<<<g, 256>>>(ta, woa, KE3, 0, 0, b_out, hnb, 0, out1, 0, Ee, nullptr, 1);
    }
}